// round 2
// baseline (speedup 1.0000x reference)
#include <cuda_runtime.h>
#include <math.h>

#define NN 100000
#define EIN 1600000
#define ETOT (EIN + NN)

// ------------------------- scratch (static device globals) -------------------
__device__ float g_h1[NN * 128];    // layer1 linear out  [N,4,32]
__device__ float g_agg1[NN * 128];  // layer1 GAT out (pre-ELU)
__device__ float g_h2[NN * 64];     // layer2 linear out  [N,4,16]
__device__ float g_asrc1[NN * 4], g_adst1[NN * 4], g_m1[NN * 4], g_den1[NN * 4];
__device__ float g_asrc2[NN * 4], g_adst2[NN * 4], g_m2[NN * 4], g_den2[NN * 4];

// ------------------------- helpers -------------------------------------------
__device__ __forceinline__ void atomicMaxF(float* addr, float v) {
    if (v >= 0.f) atomicMax((int*)addr, __float_as_int(v));
    else          atomicMin((unsigned int*)addr, __float_as_uint(v));
}

__device__ __forceinline__ void red_add_v4(float* p, float4 v) {
    asm volatile("red.global.add.v4.f32 [%0], {%1,%2,%3,%4};"
                 :: "l"(p), "f"(v.x), "f"(v.y), "f"(v.z), "f"(v.w) : "memory");
}
__device__ __forceinline__ void red_add_v2(float* p, float2 v) {
    asm volatile("red.global.add.v2.f32 [%0], {%1,%2};"
                 :: "l"(p), "f"(v.x), "f"(v.y) : "memory");
}

__device__ __forceinline__ float lrelu(float x) { return x > 0.f ? x : 0.2f * x; }

// ------------------------- GEMM: Y[N, NOUT] = act(X[N,128]) @ W[128,NOUT] ----
template <int NOUT, bool ELUIN>
__global__ void gemm_kernel(const float* __restrict__ X, const float* __restrict__ W,
                            float* __restrict__ Y) {
    constexpr int K = 128, BM = 64, KC = 32;
    constexpr int CV = NOUT / 32;  // cols per thread (4 or 2)
    __shared__ float xs[BM][KC];
    __shared__ float ws[KC][NOUT];

    const int tid = threadIdx.x;
    const int tx = tid & 31;   // 32 col-groups
    const int ty = tid >> 5;   // 8 node-groups of 8
    const int row0 = blockIdx.x * BM;

    float acc[8][CV];
#pragma unroll
    for (int i = 0; i < 8; i++)
#pragma unroll
        for (int j = 0; j < CV; j++) acc[i][j] = 0.f;

    for (int kc = 0; kc < K / KC; kc++) {
        // load X tile: 64x32
#pragma unroll
        for (int i = 0; i < (BM * KC) / 256; i++) {
            int idx = tid + i * 256;
            int r = idx >> 5, c = idx & 31;
            int gr = row0 + r;
            float v = (gr < NN) ? X[gr * K + kc * KC + c] : 0.f;
            if (ELUIN) v = v > 0.f ? v : expm1f(v);
            xs[r][c] = v;
        }
        // load W tile: 32 x NOUT
#pragma unroll
        for (int i = 0; i < (KC * NOUT) / 256; i++) {
            int idx = tid + i * 256;
            int r = idx / NOUT, c = idx % NOUT;
            ws[r][c] = W[(kc * KC + r) * NOUT + c];
        }
        __syncthreads();
#pragma unroll
        for (int k = 0; k < KC; k++) {
            float b[CV];
#pragma unroll
            for (int j = 0; j < CV; j++) b[j] = ws[k][tx * CV + j];
#pragma unroll
            for (int i = 0; i < 8; i++) {
                float a = xs[ty * 8 + i][k];
#pragma unroll
                for (int j = 0; j < CV; j++) acc[i][j] += a * b[j];
            }
        }
        __syncthreads();
    }
#pragma unroll
    for (int i = 0; i < 8; i++) {
        int row = row0 + ty * 8 + i;
        if (row < NN) {
            if constexpr (CV == 4) {
                float4 o = make_float4(acc[i][0], acc[i][1], acc[i][2], acc[i][3]);
                *reinterpret_cast<float4*>(&Y[row * NOUT + tx * 4]) = o;
            } else {
                float2 o = make_float2(acc[i][0], acc[i][1]);
                *reinterpret_cast<float2*>(&Y[row * NOUT + tx * 2]) = o;
            }
        }
    }
}

// ------------------------- per-node attention coefficients -------------------
// one warp per node; lanes 0-7 -> head 0, 8-15 -> head 1, ...
template <int DHEAD>  // 32 (layer1) or 16 (layer2)
__global__ void alpha_kernel(const float* __restrict__ h, const float* __restrict__ a_src,
                             const float* __restrict__ a_dst,
                             float* __restrict__ asrc, float* __restrict__ adst) {
    int w = (blockIdx.x * blockDim.x + threadIdx.x) >> 5;
    if (w >= NN) return;
    int lane = threadIdx.x & 31;
    int head = lane >> 3, sub = lane & 7;
    constexpr int V = DHEAD / 8;
    const float* hp = h + (size_t)w * (4 * DHEAD) + head * DHEAD + sub * V;
    const float* ap = a_src + head * DHEAD + sub * V;
    const float* bp = a_dst + head * DHEAD + sub * V;
    float ps = 0.f, pd = 0.f;
#pragma unroll
    for (int v = 0; v < V; v++) {
        float x = hp[v];
        ps += x * ap[v];
        pd += x * bp[v];
    }
#pragma unroll
    for (int off = 4; off >= 1; off >>= 1) {
        ps += __shfl_xor_sync(0xffffffffu, ps, off);
        pd += __shfl_xor_sync(0xffffffffu, pd, off);
    }
    if (sub == 0) {
        asrc[w * 4 + head] = ps;
        adst[w * 4 + head] = pd;
    }
}

// ------------------------- init: agg=bias, m=-inf, den=0 ---------------------
template <int DT>
__global__ void init_kernel(float* __restrict__ agg, const float* __restrict__ b,
                            float* __restrict__ m, float* __restrict__ den) {
    int i = blockIdx.x * blockDim.x + threadIdx.x;
    if (i < NN * DT) agg[i] = b[i & (DT - 1)];
    if (i < NN * 4) { m[i] = -INFINITY; den[i] = 0.f; }
}

// ------------------------- edge pass 1: segment max --------------------------
__global__ void edge_max_kernel(const float* __restrict__ asrc, const float* __restrict__ adst,
                                const int* __restrict__ ei, float* __restrict__ m) {
    int e = blockIdx.x * blockDim.x + threadIdx.x;
    if (e >= ETOT) return;
    int s, d;
    if (e < EIN) { s = ei[e]; d = ei[EIN + e]; } else { s = d = e - EIN; }
    float4 av = *reinterpret_cast<const float4*>(asrc + s * 4);
    float4 dv = *reinterpret_cast<const float4*>(adst + d * 4);
    atomicMaxF(&m[d * 4 + 0], lrelu(av.x + dv.x));
    atomicMaxF(&m[d * 4 + 1], lrelu(av.y + dv.y));
    atomicMaxF(&m[d * 4 + 2], lrelu(av.z + dv.z));
    atomicMaxF(&m[d * 4 + 3], lrelu(av.w + dv.w));
}

// ------------------------- edge pass 2: segment sum of exp -------------------
__global__ void edge_sum_kernel(const float* __restrict__ asrc, const float* __restrict__ adst,
                                const int* __restrict__ ei, const float* __restrict__ m,
                                float* __restrict__ den) {
    int e = blockIdx.x * blockDim.x + threadIdx.x;
    if (e >= ETOT) return;
    int s, d;
    if (e < EIN) { s = ei[e]; d = ei[EIN + e]; } else { s = d = e - EIN; }
    float4 av = *reinterpret_cast<const float4*>(asrc + s * 4);
    float4 dv = *reinterpret_cast<const float4*>(adst + d * 4);
    float4 mv = *reinterpret_cast<const float4*>(m + d * 4);
    atomicAdd(&den[d * 4 + 0], expf(lrelu(av.x + dv.x) - mv.x));
    atomicAdd(&den[d * 4 + 1], expf(lrelu(av.y + dv.y) - mv.y));
    atomicAdd(&den[d * 4 + 2], expf(lrelu(av.z + dv.z) - mv.z));
    atomicAdd(&den[d * 4 + 3], expf(lrelu(av.w + dv.w) - mv.w));
}

// ------------------------- edge pass 3: weighted aggregation -----------------
// one warp per edge; lane covers DT/32 consecutive features; head = lane/8
template <int DT>  // 128 (layer1) or 64 (layer2)
__global__ void aggregate_kernel(const float* __restrict__ h, const float* __restrict__ asrc,
                                 const float* __restrict__ adst, const float* __restrict__ m,
                                 const float* __restrict__ den, const int* __restrict__ ei,
                                 float* __restrict__ out) {
    long long gw = ((long long)blockIdx.x * blockDim.x + threadIdx.x) >> 5;
    if (gw >= ETOT) return;
    int e = (int)gw;
    int lane = threadIdx.x & 31;
    int s, d;
    if (e < EIN) { s = ei[e]; d = ei[EIN + e]; } else { s = d = e - EIN; }
    int head = lane >> 3;
    float sa = asrc[s * 4 + head];
    float da = adst[d * 4 + head];
    float mm = m[d * 4 + head];
    float dn = den[d * 4 + head];
    float alpha = expf(lrelu(sa + da) - mm) / (dn + 1e-16f);
    constexpr int V = DT / 32;
    if constexpr (V == 4) {
        float4 hv = *reinterpret_cast<const float4*>(h + (size_t)s * DT + lane * 4);
        float4 r = make_float4(alpha * hv.x, alpha * hv.y, alpha * hv.z, alpha * hv.w);
        red_add_v4(out + (size_t)d * DT + lane * 4, r);
    } else {
        float2 hv = *reinterpret_cast<const float2*>(h + (size_t)s * DT + lane * 2);
        float2 r = make_float2(alpha * hv.x, alpha * hv.y);
        red_add_v2(out + (size_t)d * DT + lane * 2, r);
    }
}

// ------------------------- log_softmax in place over 64 classes --------------
__global__ void log_softmax_kernel(float* __restrict__ out) {
    int w = (blockIdx.x * blockDim.x + threadIdx.x) >> 5;
    if (w >= NN) return;
    int lane = threadIdx.x & 31;
    float2 v = *reinterpret_cast<const float2*>(out + (size_t)w * 64 + lane * 2);
    float mx = fmaxf(v.x, v.y);
#pragma unroll
    for (int off = 16; off >= 1; off >>= 1)
        mx = fmaxf(mx, __shfl_xor_sync(0xffffffffu, mx, off));
    float sm = expf(v.x - mx) + expf(v.y - mx);
#pragma unroll
    for (int off = 16; off >= 1; off >>= 1)
        sm += __shfl_xor_sync(0xffffffffu, sm, off);
    float ls = logf(sm);
    float2 o = make_float2(v.x - mx - ls, v.y - mx - ls);
    *reinterpret_cast<float2*>(out + (size_t)w * 64 + lane * 2) = o;
}

// ------------------------- launch --------------------------------------------
extern "C" void kernel_launch(void* const* d_in, const int* in_sizes, int n_in,
                              void* d_out, int out_size) {
    const float* x        = (const float*)d_in[0];
    const int*   ei       = (const int*)d_in[1];
    const float* W1       = (const float*)d_in[2];
    const float* att_src1 = (const float*)d_in[3];
    const float* att_dst1 = (const float*)d_in[4];
    const float* b1       = (const float*)d_in[5];
    const float* W2       = (const float*)d_in[6];
    const float* att_src2 = (const float*)d_in[7];
    const float* att_dst2 = (const float*)d_in[8];
    const float* b2       = (const float*)d_in[9];
    float* out = (float*)d_out;

    float *h1, *agg1, *h2;
    float *asrc1, *adst1, *m1, *den1, *asrc2, *adst2, *m2, *den2;
    cudaGetSymbolAddress((void**)&h1, g_h1);
    cudaGetSymbolAddress((void**)&agg1, g_agg1);
    cudaGetSymbolAddress((void**)&h2, g_h2);
    cudaGetSymbolAddress((void**)&asrc1, g_asrc1);
    cudaGetSymbolAddress((void**)&adst1, g_adst1);
    cudaGetSymbolAddress((void**)&m1, g_m1);
    cudaGetSymbolAddress((void**)&den1, g_den1);
    cudaGetSymbolAddress((void**)&asrc2, g_asrc2);
    cudaGetSymbolAddress((void**)&adst2, g_adst2);
    cudaGetSymbolAddress((void**)&m2, g_m2);
    cudaGetSymbolAddress((void**)&den2, g_den2);

    const int TB = 256;
    const int gemm_blocks = (NN + 63) / 64;
    const int node_warp_blocks = (NN * 32 + TB - 1) / TB;   // warp per node
    const int edge_blocks = (ETOT + TB - 1) / TB;
    const int agg_blocks = (int)(((long long)ETOT * 32 + TB - 1) / TB);

    // ---- layer 1 ----
    gemm_kernel<128, false><<<gemm_blocks, TB>>>(x, W1, h1);
    alpha_kernel<32><<<node_warp_blocks, TB>>>(h1, att_src1, att_dst1, asrc1, adst1);
    init_kernel<128><<<(NN * 128 + TB - 1) / TB, TB>>>(agg1, b1, m1, den1);
    edge_max_kernel<<<edge_blocks, TB>>>(asrc1, adst1, ei, m1);
    edge_sum_kernel<<<edge_blocks, TB>>>(asrc1, adst1, ei, m1, den1);
    aggregate_kernel<128><<<agg_blocks, TB>>>(h1, asrc1, adst1, m1, den1, ei, agg1);

    // ---- layer 2 (ELU fused into GEMM load) ----
    gemm_kernel<64, true><<<gemm_blocks, TB>>>(agg1, W2, h2);
    alpha_kernel<16><<<node_warp_blocks, TB>>>(h2, att_src2, att_dst2, asrc2, adst2);
    init_kernel<64><<<(NN * 64 + TB - 1) / TB, TB>>>(out, b2, m2, den2);
    edge_max_kernel<<<edge_blocks, TB>>>(asrc2, adst2, ei, m2);
    edge_sum_kernel<<<edge_blocks, TB>>>(asrc2, adst2, ei, m2, den2);
    aggregate_kernel<64><<<agg_blocks, TB>>>(h2, asrc2, adst2, m2, den2, ei, out);

    // ---- log_softmax over 64 classes, in place ----
    log_softmax_kernel<<<node_warp_blocks, TB>>>(out);
}

// round 3
// speedup vs baseline: 1.0102x; 1.0102x over previous
#include <cuda_runtime.h>
#include <math.h>

#define NN 100000
#define EIN 1600000
#define ETOT (EIN + NN)

// ------------------------- scratch (static device globals) -------------------
__device__ float g_h1[NN * 128];    // layer1 linear out  [N,4,32]
__device__ float g_agg1[NN * 128];  // layer1 GAT out (pre-ELU)
__device__ float g_h2[NN * 64];     // layer2 linear out  [N,4,16]
__device__ float g_asrc1[NN * 4], g_adst1[NN * 4], g_m1[NN * 4], g_den1[NN * 4];
__device__ float g_asrc2[NN * 4], g_adst2[NN * 4], g_m2[NN * 4], g_den2[NN * 4];

// ------------------------- helpers -------------------------------------------
__device__ __forceinline__ void atomicMaxF(float* addr, float v) {
    if (v >= 0.f) atomicMax((int*)addr, __float_as_int(v));
    else          atomicMin((unsigned int*)addr, __float_as_uint(v));
}

__device__ __forceinline__ void red_add_v4(float* p, float4 v) {
    asm volatile("red.global.add.v4.f32 [%0], {%1,%2,%3,%4};"
                 :: "l"(p), "f"(v.x), "f"(v.y), "f"(v.z), "f"(v.w) : "memory");
}
__device__ __forceinline__ void red_add_v2(float* p, float2 v) {
    asm volatile("red.global.add.v2.f32 [%0], {%1,%2};"
                 :: "l"(p), "f"(v.x), "f"(v.y) : "memory");
}

__device__ __forceinline__ float lrelu(float x) { return x > 0.f ? x : 0.2f * x; }

// ------------------------- GEMM: Y[N, NOUT] = act(X[N,128]) @ W[128,NOUT] ----
template <int NOUT, bool ELUIN>
__global__ void gemm_kernel(const float* __restrict__ X, const float* __restrict__ W,
                            float* __restrict__ Y) {
    constexpr int K = 128, BM = 64, KC = 32;
    constexpr int CV = NOUT / 32;  // cols per thread (4 or 2)
    __shared__ float xs[BM][KC];
    __shared__ float ws[KC][NOUT];

    const int tid = threadIdx.x;
    const int tx = tid & 31;   // 32 col-groups
    const int ty = tid >> 5;   // 8 node-groups of 8
    const int row0 = blockIdx.x * BM;

    float acc[8][CV];
#pragma unroll
    for (int i = 0; i < 8; i++)
#pragma unroll
        for (int j = 0; j < CV; j++) acc[i][j] = 0.f;

    for (int kc = 0; kc < K / KC; kc++) {
        // load X tile: 64x32
#pragma unroll
        for (int i = 0; i < (BM * KC) / 256; i++) {
            int idx = tid + i * 256;
            int r = idx >> 5, c = idx & 31;
            int gr = row0 + r;
            float v = (gr < NN) ? X[gr * K + kc * KC + c] : 0.f;
            if (ELUIN) v = v > 0.f ? v : expm1f(v);
            xs[r][c] = v;
        }
        // load W tile: 32 x NOUT
#pragma unroll
        for (int i = 0; i < (KC * NOUT) / 256; i++) {
            int idx = tid + i * 256;
            int r = idx / NOUT, c = idx % NOUT;
            ws[r][c] = W[(kc * KC + r) * NOUT + c];
        }
        __syncthreads();
#pragma unroll
        for (int k = 0; k < KC; k++) {
            float b[CV];
#pragma unroll
            for (int j = 0; j < CV; j++) b[j] = ws[k][tx * CV + j];
#pragma unroll
            for (int i = 0; i < 8; i++) {
                float a = xs[ty * 8 + i][k];
#pragma unroll
                for (int j = 0; j < CV; j++) acc[i][j] += a * b[j];
            }
        }
        __syncthreads();
    }
#pragma unroll
    for (int i = 0; i < 8; i++) {
        int row = row0 + ty * 8 + i;
        if (row < NN) {
            if constexpr (CV == 4) {
                float4 o = make_float4(acc[i][0], acc[i][1], acc[i][2], acc[i][3]);
                *reinterpret_cast<float4*>(&Y[row * NOUT + tx * 4]) = o;
            } else {
                float2 o = make_float2(acc[i][0], acc[i][1]);
                *reinterpret_cast<float2*>(&Y[row * NOUT + tx * 2]) = o;
            }
        }
    }
}

// ------------------------- per-node attention coefficients -------------------
// one warp per node; lanes 0-7 -> head 0, 8-15 -> head 1, ...
template <int DHEAD>  // 32 (layer1) or 16 (layer2)
__global__ void alpha_kernel(const float* __restrict__ h, const float* __restrict__ a_src,
                             const float* __restrict__ a_dst,
                             float* __restrict__ asrc, float* __restrict__ adst) {
    int w = (blockIdx.x * blockDim.x + threadIdx.x) >> 5;
    if (w >= NN) return;
    int lane = threadIdx.x & 31;
    int head = lane >> 3, sub = lane & 7;
    constexpr int V = DHEAD / 8;
    const float* hp = h + (size_t)w * (4 * DHEAD) + head * DHEAD + sub * V;
    const float* ap = a_src + head * DHEAD + sub * V;
    const float* bp = a_dst + head * DHEAD + sub * V;
    float ps = 0.f, pd = 0.f;
#pragma unroll
    for (int v = 0; v < V; v++) {
        float x = hp[v];
        ps += x * ap[v];
        pd += x * bp[v];
    }
#pragma unroll
    for (int off = 4; off >= 1; off >>= 1) {
        ps += __shfl_xor_sync(0xffffffffu, ps, off);
        pd += __shfl_xor_sync(0xffffffffu, pd, off);
    }
    if (sub == 0) {
        asrc[w * 4 + head] = ps;
        adst[w * 4 + head] = pd;
    }
}

// ------------------------- init: agg=bias, m=-inf, den=0 ---------------------
template <int DT>
__global__ void init_kernel(float* __restrict__ agg, const float* __restrict__ b,
                            float* __restrict__ m, float* __restrict__ den) {
    int i = blockIdx.x * blockDim.x + threadIdx.x;
    if (i < NN * DT) agg[i] = b[i & (DT - 1)];
    if (i < NN * 4) { m[i] = -INFINITY; den[i] = 0.f; }
}

// ------------------------- edge pass 1: segment max --------------------------
__global__ void edge_max_kernel(const float* __restrict__ asrc, const float* __restrict__ adst,
                                const int* __restrict__ ei, float* __restrict__ m) {
    int e = blockIdx.x * blockDim.x + threadIdx.x;
    if (e >= ETOT) return;
    int s, d;
    if (e < EIN) { s = ei[e]; d = ei[EIN + e]; } else { s = d = e - EIN; }
    float4 av = *reinterpret_cast<const float4*>(asrc + s * 4);
    float4 dv = *reinterpret_cast<const float4*>(adst + d * 4);
    atomicMaxF(&m[d * 4 + 0], lrelu(av.x + dv.x));
    atomicMaxF(&m[d * 4 + 1], lrelu(av.y + dv.y));
    atomicMaxF(&m[d * 4 + 2], lrelu(av.z + dv.z));
    atomicMaxF(&m[d * 4 + 3], lrelu(av.w + dv.w));
}

// ------------------------- edge pass 2: segment sum of exp -------------------
__global__ void edge_sum_kernel(const float* __restrict__ asrc, const float* __restrict__ adst,
                                const int* __restrict__ ei, const float* __restrict__ m,
                                float* __restrict__ den) {
    int e = blockIdx.x * blockDim.x + threadIdx.x;
    if (e >= ETOT) return;
    int s, d;
    if (e < EIN) { s = ei[e]; d = ei[EIN + e]; } else { s = d = e - EIN; }
    float4 av = *reinterpret_cast<const float4*>(asrc + s * 4);
    float4 dv = *reinterpret_cast<const float4*>(adst + d * 4);
    float4 mv = *reinterpret_cast<const float4*>(m + d * 4);
    atomicAdd(&den[d * 4 + 0], expf(lrelu(av.x + dv.x) - mv.x));
    atomicAdd(&den[d * 4 + 1], expf(lrelu(av.y + dv.y) - mv.y));
    atomicAdd(&den[d * 4 + 2], expf(lrelu(av.z + dv.z) - mv.z));
    atomicAdd(&den[d * 4 + 3], expf(lrelu(av.w + dv.w) - mv.w));
}

// ------------------------- edge pass 3: weighted aggregation -----------------
// one warp per edge; lane covers DT/32 consecutive features; head = lane/8
template <int DT>  // 128 (layer1) or 64 (layer2)
__global__ void aggregate_kernel(const float* __restrict__ h, const float* __restrict__ asrc,
                                 const float* __restrict__ adst, const float* __restrict__ m,
                                 const float* __restrict__ den, const int* __restrict__ ei,
                                 float* __restrict__ out) {
    long long gw = ((long long)blockIdx.x * blockDim.x + threadIdx.x) >> 5;
    if (gw >= ETOT) return;
    int e = (int)gw;
    int lane = threadIdx.x & 31;
    int s, d;
    if (e < EIN) { s = ei[e]; d = ei[EIN + e]; } else { s = d = e - EIN; }
    int head = lane >> 3;
    float sa = asrc[s * 4 + head];
    float da = adst[d * 4 + head];
    float mm = m[d * 4 + head];
    float dn = den[d * 4 + head];
    float alpha = expf(lrelu(sa + da) - mm) / (dn + 1e-16f);
    constexpr int V = DT / 32;
    if constexpr (V == 4) {
        float4 hv = *reinterpret_cast<const float4*>(h + (size_t)s * DT + lane * 4);
        float4 r = make_float4(alpha * hv.x, alpha * hv.y, alpha * hv.z, alpha * hv.w);
        red_add_v4(out + (size_t)d * DT + lane * 4, r);
    } else {
        float2 hv = *reinterpret_cast<const float2*>(h + (size_t)s * DT + lane * 2);
        float2 r = make_float2(alpha * hv.x, alpha * hv.y);
        red_add_v2(out + (size_t)d * DT + lane * 2, r);
    }
}

// ------------------------- log_softmax in place over 64 classes --------------
__global__ void log_softmax_kernel(float* __restrict__ out) {
    int w = (blockIdx.x * blockDim.x + threadIdx.x) >> 5;
    if (w >= NN) return;
    int lane = threadIdx.x & 31;
    float2 v = *reinterpret_cast<const float2*>(out + (size_t)w * 64 + lane * 2);
    float mx = fmaxf(v.x, v.y);
#pragma unroll
    for (int off = 16; off >= 1; off >>= 1)
        mx = fmaxf(mx, __shfl_xor_sync(0xffffffffu, mx, off));
    float sm = expf(v.x - mx) + expf(v.y - mx);
#pragma unroll
    for (int off = 16; off >= 1; off >>= 1)
        sm += __shfl_xor_sync(0xffffffffu, sm, off);
    float ls = logf(sm);
    float2 o = make_float2(v.x - mx - ls, v.y - mx - ls);
    *reinterpret_cast<float2*>(out + (size_t)w * 64 + lane * 2) = o;
}

// ------------------------- launch --------------------------------------------
extern "C" void kernel_launch(void* const* d_in, const int* in_sizes, int n_in,
                              void* d_out, int out_size) {
    const float* x        = (const float*)d_in[0];
    const int*   ei       = (const int*)d_in[1];
    const float* W1       = (const float*)d_in[2];
    const float* att_src1 = (const float*)d_in[3];
    const float* att_dst1 = (const float*)d_in[4];
    const float* b1       = (const float*)d_in[5];
    const float* W2       = (const float*)d_in[6];
    const float* att_src2 = (const float*)d_in[7];
    const float* att_dst2 = (const float*)d_in[8];
    const float* b2       = (const float*)d_in[9];
    float* out = (float*)d_out;

    float *h1, *agg1, *h2;
    float *asrc1, *adst1, *m1, *den1, *asrc2, *adst2, *m2, *den2;
    cudaGetSymbolAddress((void**)&h1, g_h1);
    cudaGetSymbolAddress((void**)&agg1, g_agg1);
    cudaGetSymbolAddress((void**)&h2, g_h2);
    cudaGetSymbolAddress((void**)&asrc1, g_asrc1);
    cudaGetSymbolAddress((void**)&adst1, g_adst1);
    cudaGetSymbolAddress((void**)&m1, g_m1);
    cudaGetSymbolAddress((void**)&den1, g_den1);
    cudaGetSymbolAddress((void**)&asrc2, g_asrc2);
    cudaGetSymbolAddress((void**)&adst2, g_adst2);
    cudaGetSymbolAddress((void**)&m2, g_m2);
    cudaGetSymbolAddress((void**)&den2, g_den2);

    const int TB = 256;
    const int gemm_blocks = (NN + 63) / 64;
    const int node_warp_blocks = (NN * 32 + TB - 1) / TB;   // warp per node
    const int edge_blocks = (ETOT + TB - 1) / TB;
    const int agg_blocks = (int)(((long long)ETOT * 32 + TB - 1) / TB);

    // ---- layer 1 ----
    gemm_kernel<128, false><<<gemm_blocks, TB>>>(x, W1, h1);
    alpha_kernel<32><<<node_warp_blocks, TB>>>(h1, att_src1, att_dst1, asrc1, adst1);
    init_kernel<128><<<(NN * 128 + TB - 1) / TB, TB>>>(agg1, b1, m1, den1);
    edge_max_kernel<<<edge_blocks, TB>>>(asrc1, adst1, ei, m1);
    edge_sum_kernel<<<edge_blocks, TB>>>(asrc1, adst1, ei, m1, den1);
    aggregate_kernel<128><<<agg_blocks, TB>>>(h1, asrc1, adst1, m1, den1, ei, agg1);

    // ---- layer 2 (ELU fused into GEMM load) ----
    gemm_kernel<64, true><<<gemm_blocks, TB>>>(agg1, W2, h2);
    alpha_kernel<16><<<node_warp_blocks, TB>>>(h2, att_src2, att_dst2, asrc2, adst2);
    init_kernel<64><<<(NN * 64 + TB - 1) / TB, TB>>>(out, b2, m2, den2);
    edge_max_kernel<<<edge_blocks, TB>>>(asrc2, adst2, ei, m2);
    edge_sum_kernel<<<edge_blocks, TB>>>(asrc2, adst2, ei, m2, den2);
    aggregate_kernel<64><<<agg_blocks, TB>>>(h2, asrc2, adst2, m2, den2, ei, out);

    // ---- log_softmax over 64 classes, in place ----
    log_softmax_kernel<<<node_warp_blocks, TB>>>(out);
}

// round 4
// speedup vs baseline: 1.7809x; 1.7629x over previous
#include <cuda_runtime.h>
#include <math.h>

#define NN 100000
#define EIN 1600000
#define ETOT (EIN + NN)

// ------------------------- scratch (static device globals) -------------------
__device__ float g_h1[NN * 128];    // layer1 linear out  [N,4,32]
__device__ float g_agg1[NN * 128];  // layer1 num -> normalized GAT out (ELU'd)
__device__ float g_h2[NN * 64];     // layer2 linear out  [N,4,16]
__device__ float g_asrc1[NN * 4], g_adst1[NN * 4], g_den1[NN * 4];
__device__ float g_asrc2[NN * 4], g_adst2[NN * 4], g_den2[NN * 4];

// ------------------------- helpers -------------------------------------------
__device__ __forceinline__ void red_add_v4(float* p, float4 v) {
    asm volatile("red.global.add.v4.f32 [%0], {%1,%2,%3,%4};"
                 :: "l"(p), "f"(v.x), "f"(v.y), "f"(v.z), "f"(v.w) : "memory");
}

__device__ __forceinline__ float lrelu(float x) { return x > 0.f ? x : 0.2f * x; }

// ------------------------- GEMM + fused attention-coefficient epilogue -------
// Y[N, NOUT] = X[N,128] @ W[128,NOUT]
// Epilogue: asrc[n,h] = sum_f Y[n,h,f]*a_src[h,f], same for adst (per-head
// segmented warp reduction: each warp holds a full output row across lanes).
template <int NOUT>
__global__ void gemm_kernel(const float* __restrict__ X, const float* __restrict__ W,
                            const float* __restrict__ ASRC, const float* __restrict__ ADST,
                            float* __restrict__ Y,
                            float* __restrict__ asrc, float* __restrict__ adst) {
    constexpr int K = 128, BM = 64, KC = 32;
    constexpr int CV = NOUT / 32;  // cols per thread (4 or 2)
    __shared__ float xs[BM][KC + 1];               // +1 pad: kill 8-way conflicts
    __shared__ __align__(16) float ws[KC][NOUT];

    const int tid = threadIdx.x;
    const int tx = tid & 31;   // 32 col-groups (one warp holds a full row)
    const int ty = tid >> 5;   // 8 node-groups of 8
    const int row0 = blockIdx.x * BM;

    float acc[8][CV];
#pragma unroll
    for (int i = 0; i < 8; i++)
#pragma unroll
        for (int j = 0; j < CV; j++) acc[i][j] = 0.f;

    for (int kc = 0; kc < K / KC; kc++) {
#pragma unroll
        for (int i = 0; i < (BM * KC) / 256; i++) {
            int idx = tid + i * 256;
            int r = idx >> 5, c = idx & 31;
            int gr = row0 + r;
            xs[r][c] = (gr < NN) ? X[gr * K + kc * KC + c] : 0.f;
        }
#pragma unroll
        for (int i = 0; i < (KC * NOUT) / 256; i++) {
            int idx = tid + i * 256;
            int r = idx / NOUT, c = idx % NOUT;
            ws[r][c] = W[(kc * KC + r) * NOUT + c];
        }
        __syncthreads();
#pragma unroll
        for (int k = 0; k < KC; k++) {
            float b[CV];
            if constexpr (CV == 4) {
                float4 bv = reinterpret_cast<const float4*>(&ws[k][0])[tx];
                b[0] = bv.x; b[1] = bv.y; b[2] = bv.z; b[3] = bv.w;
            } else {
                float2 bv = reinterpret_cast<const float2*>(&ws[k][0])[tx];
                b[0] = bv.x; b[1] = bv.y;
            }
#pragma unroll
            for (int i = 0; i < 8; i++) {
                float a = xs[ty * 8 + i][k];
#pragma unroll
                for (int j = 0; j < CV; j++) acc[i][j] += a * b[j];
            }
        }
        __syncthreads();
    }

    // attention vectors for this lane's features (f = tx*CV + j, head = tx>>3)
    float as_[CV], ad_[CV];
#pragma unroll
    for (int j = 0; j < CV; j++) {
        as_[j] = ASRC[tx * CV + j];
        ad_[j] = ADST[tx * CV + j];
    }

#pragma unroll
    for (int i = 0; i < 8; i++) {
        int row = row0 + ty * 8 + i;
        float ps = 0.f, pd = 0.f;
#pragma unroll
        for (int j = 0; j < CV; j++) {
            ps += acc[i][j] * as_[j];
            pd += acc[i][j] * ad_[j];
        }
        // per-head reduce over 8-lane groups
#pragma unroll
        for (int off = 4; off >= 1; off >>= 1) {
            ps += __shfl_xor_sync(0xffffffffu, ps, off);
            pd += __shfl_xor_sync(0xffffffffu, pd, off);
        }
        if (row < NN) {
            if constexpr (CV == 4) {
                float4 o = make_float4(acc[i][0], acc[i][1], acc[i][2], acc[i][3]);
                *reinterpret_cast<float4*>(&Y[row * NOUT + tx * 4]) = o;
            } else {
                float2 o = make_float2(acc[i][0], acc[i][1]);
                *reinterpret_cast<float2*>(&Y[row * NOUT + tx * 2]) = o;
            }
            if ((tx & 7) == 0) {
                asrc[row * 4 + (tx >> 3)] = ps;
                adst[row * 4 + (tx >> 3)] = pd;
            }
        }
    }
}

// ------------------------- single fused edge pass, DT=128 (warp/edge) --------
// num[d] += exp(e)*h[s] ; den[d] += exp(e)   (normalization deferred)
__global__ void edge_agg128_kernel(const float* __restrict__ h,
                                   const float* __restrict__ asrc,
                                   const float* __restrict__ adst,
                                   const int* __restrict__ ei,
                                   float* __restrict__ num, float* __restrict__ den) {
    long long gw = ((long long)blockIdx.x * blockDim.x + threadIdx.x) >> 5;
    if (gw >= ETOT) return;
    int e = (int)gw;
    int lane = threadIdx.x & 31;
    int s, d;
    if (e < EIN) { s = ei[e]; d = ei[EIN + e]; } else { s = d = e - EIN; }
    int head = lane >> 3;
    float w = expf(lrelu(asrc[s * 4 + head] + adst[d * 4 + head]));
    float4 hv = *reinterpret_cast<const float4*>(h + (size_t)s * 128 + lane * 4);
    red_add_v4(num + (size_t)d * 128 + lane * 4,
               make_float4(w * hv.x, w * hv.y, w * hv.z, w * hv.w));
    if ((lane & 7) == 0) atomicAdd(&den[d * 4 + head], w);
}

// ------------------------- single fused edge pass, DT=64 (half-warp/edge) ----
__global__ void edge_agg64_kernel(const float* __restrict__ h,
                                  const float* __restrict__ asrc,
                                  const float* __restrict__ adst,
                                  const int* __restrict__ ei,
                                  float* __restrict__ num, float* __restrict__ den) {
    long long gi = (long long)blockIdx.x * blockDim.x + threadIdx.x;
    long long ge = gi >> 4;
    if (ge >= ETOT) return;
    int e = (int)ge;
    int sub = (int)(gi & 15);
    int s, d;
    if (e < EIN) { s = ei[e]; d = ei[EIN + e]; } else { s = d = e - EIN; }
    int head = sub >> 2;
    float w = expf(lrelu(asrc[s * 4 + head] + adst[d * 4 + head]));
    float4 hv = *reinterpret_cast<const float4*>(h + (size_t)s * 64 + sub * 4);
    red_add_v4(num + (size_t)d * 64 + sub * 4,
               make_float4(w * hv.x, w * hv.y, w * hv.z, w * hv.w));
    if ((sub & 3) == 0) atomicAdd(&den[d * 4 + head], w);
}

// ------------------------- layer-1 normalize: num/den + bias, ELU (in place) -
__global__ void norm1_kernel(float* __restrict__ num, const float* __restrict__ den,
                             const float* __restrict__ b1) {
    int i = blockIdx.x * blockDim.x + threadIdx.x;  // one float4 per thread
    if (i >= NN * 32) return;
    int node = i >> 5;
    int q = i & 31;            // float4 index within row; head = q>>3
    float dn = den[node * 4 + (q >> 3)] + 1e-16f;
    float inv = 1.f / dn;
    float4 v = reinterpret_cast<float4*>(num)[i];
    const float4 b = reinterpret_cast<const float4*>(b1)[q];
    v.x = v.x * inv + b.x; v.y = v.y * inv + b.y;
    v.z = v.z * inv + b.z; v.w = v.w * inv + b.w;
    v.x = v.x > 0.f ? v.x : expm1f(v.x);
    v.y = v.y > 0.f ? v.y : expm1f(v.y);
    v.z = v.z > 0.f ? v.z : expm1f(v.z);
    v.w = v.w > 0.f ? v.w : expm1f(v.w);
    reinterpret_cast<float4*>(num)[i] = v;
}

// ------------- final: layer-2 normalize + bias + log_softmax (warp/node) -----
__global__ void final_kernel(float* __restrict__ out, const float* __restrict__ den,
                             const float* __restrict__ b2) {
    int w = (blockIdx.x * blockDim.x + threadIdx.x) >> 5;
    if (w >= NN) return;
    int lane = threadIdx.x & 31;
    int f0 = lane * 2;
    int head = f0 >> 4;                       // f0 even -> f0,f0+1 same head
    float dn = den[w * 4 + head] + 1e-16f;
    float inv = 1.f / dn;
    float2 v = *reinterpret_cast<const float2*>(out + (size_t)w * 64 + f0);
    v.x = v.x * inv + b2[f0];
    v.y = v.y * inv + b2[f0 + 1];
    float mx = fmaxf(v.x, v.y);
#pragma unroll
    for (int off = 16; off >= 1; off >>= 1)
        mx = fmaxf(mx, __shfl_xor_sync(0xffffffffu, mx, off));
    float sm = expf(v.x - mx) + expf(v.y - mx);
#pragma unroll
    for (int off = 16; off >= 1; off >>= 1)
        sm += __shfl_xor_sync(0xffffffffu, sm, off);
    float ls = logf(sm);
    float2 o = make_float2(v.x - mx - ls, v.y - mx - ls);
    *reinterpret_cast<float2*>(out + (size_t)w * 64 + f0) = o;
}

// ------------------------- launch --------------------------------------------
extern "C" void kernel_launch(void* const* d_in, const int* in_sizes, int n_in,
                              void* d_out, int out_size) {
    const float* x        = (const float*)d_in[0];
    const int*   ei       = (const int*)d_in[1];
    const float* W1       = (const float*)d_in[2];
    const float* att_src1 = (const float*)d_in[3];
    const float* att_dst1 = (const float*)d_in[4];
    const float* b1       = (const float*)d_in[5];
    const float* W2       = (const float*)d_in[6];
    const float* att_src2 = (const float*)d_in[7];
    const float* att_dst2 = (const float*)d_in[8];
    const float* b2       = (const float*)d_in[9];
    float* out = (float*)d_out;

    float *h1, *agg1, *h2;
    float *asrc1, *adst1, *den1, *asrc2, *adst2, *den2;
    cudaGetSymbolAddress((void**)&h1, g_h1);
    cudaGetSymbolAddress((void**)&agg1, g_agg1);
    cudaGetSymbolAddress((void**)&h2, g_h2);
    cudaGetSymbolAddress((void**)&asrc1, g_asrc1);
    cudaGetSymbolAddress((void**)&adst1, g_adst1);
    cudaGetSymbolAddress((void**)&den1, g_den1);
    cudaGetSymbolAddress((void**)&asrc2, g_asrc2);
    cudaGetSymbolAddress((void**)&adst2, g_adst2);
    cudaGetSymbolAddress((void**)&den2, g_den2);

    const int TB = 256;
    const int gemm_blocks = (NN + 63) / 64;
    const int node_warp_blocks = (NN * 32 + TB - 1) / TB;
    const int agg128_blocks = (int)(((long long)ETOT * 32 + TB - 1) / TB);
    const int agg64_blocks  = (int)(((long long)ETOT * 16 + TB - 1) / TB);

    // ---- layer 1 ----
    cudaMemsetAsync(agg1, 0, (size_t)NN * 128 * sizeof(float));
    cudaMemsetAsync(den1, 0, (size_t)NN * 4 * sizeof(float));
    gemm_kernel<128><<<gemm_blocks, TB>>>(x, W1, att_src1, att_dst1, h1, asrc1, adst1);
    edge_agg128_kernel<<<agg128_blocks, TB>>>(h1, asrc1, adst1, ei, agg1, den1);
    norm1_kernel<<<(NN * 32 + TB - 1) / TB, TB>>>(agg1, den1, b1);

    // ---- layer 2 ----
    cudaMemsetAsync(out, 0, (size_t)NN * 64 * sizeof(float));
    cudaMemsetAsync(den2, 0, (size_t)NN * 4 * sizeof(float));
    gemm_kernel<64><<<gemm_blocks, TB>>>(agg1, W2, att_src2, att_dst2, h2, asrc2, adst2);
    edge_agg64_kernel<<<agg64_blocks, TB>>>(h2, asrc2, adst2, ei, out, den2);

    // ---- normalize + bias + log_softmax ----
    final_kernel<<<node_warp_blocks, TB>>>(out, den2, b2);
}

// round 5
// speedup vs baseline: 1.9991x; 1.1225x over previous
#include <cuda_runtime.h>
#include <math.h>

#define NN 100000
#define EIN 1600000
#define ETOT (EIN + NN)

// ------------------------- scratch (static device globals) -------------------
__device__ float g_h1[NN * 128];    // layer1 linear out  [N,4,32]
__device__ float g_agg1[NN * 128];  // layer1 GAT out (normalized, biased, ELU)
__device__ float g_h2[NN * 64];     // layer2 linear out  [N,4,16]
__device__ float g_asrc1[NN * 4], g_adst1[NN * 4];
__device__ float g_asrc2[NN * 4], g_adst2[NN * 4];
__device__ int   g_deg[NN + 1];     // in-degree (incl self loop) -> consumed
__device__ int   g_wptr[NN + 1];    // running write ptr for scatter
__device__ int   g_rowptr[NN + 1];  // CSR row pointers (by dst)
__device__ int   g_esrc[ETOT];      // CSR src indices

// ------------------------- helpers -------------------------------------------
__device__ __forceinline__ float lrelu(float x) { return x > 0.f ? x : 0.2f * x; }

// ------------------------- CSR build -----------------------------------------
__global__ void init_deg_kernel(int* __restrict__ deg) {
    int i = blockIdx.x * blockDim.x + threadIdx.x;
    if (i < NN) deg[i] = 1;  // self loop
}

__global__ void hist_kernel(const int* __restrict__ ei, int* __restrict__ deg) {
    int e = blockIdx.x * blockDim.x + threadIdx.x;
    if (e < EIN) atomicAdd(&deg[ei[EIN + e]], 1);
}

// single-block exclusive scan over deg -> rowptr & wptr
__global__ void scan_kernel(const int* __restrict__ deg, int* __restrict__ rowptr,
                            int* __restrict__ wptr) {
    __shared__ int psum[1024];
    const int t = threadIdx.x;
    const int CH = (NN + 1023) / 1024;  // 98
    const int base = t * CH;
    int sum = 0;
    for (int i = 0; i < CH; i++) {
        int idx = base + i;
        if (idx < NN) sum += deg[idx];
    }
    psum[t] = sum;
    __syncthreads();
    // inclusive Hillis-Steele scan
    for (int off = 1; off < 1024; off <<= 1) {
        int v = (t >= off) ? psum[t - off] : 0;
        __syncthreads();
        psum[t] += v;
        __syncthreads();
    }
    int running = psum[t] - sum;  // exclusive base for this thread's chunk
    for (int i = 0; i < CH; i++) {
        int idx = base + i;
        if (idx < NN) {
            int dv = deg[idx];
            rowptr[idx] = running;
            wptr[idx] = running;
            running += dv;
        }
    }
    if (t == 0) rowptr[NN] = ETOT;
}

__global__ void scatter_kernel(const int* __restrict__ ei, int* __restrict__ wptr,
                               int* __restrict__ esrc) {
    int e = blockIdx.x * blockDim.x + threadIdx.x;
    if (e >= ETOT) return;
    int s, d;
    if (e < EIN) { s = ei[e]; d = ei[EIN + e]; } else { s = d = e - EIN; }
    int pos = atomicAdd(&wptr[d], 1);
    esrc[pos] = s;
}

// ------------------------- GEMM + fused attention-coefficient epilogue -------
template <int NOUT>
__global__ void gemm_kernel(const float* __restrict__ X, const float* __restrict__ W,
                            const float* __restrict__ ASRC, const float* __restrict__ ADST,
                            float* __restrict__ Y,
                            float* __restrict__ asrc, float* __restrict__ adst) {
    constexpr int K = 128, BM = 64, KC = 32;
    constexpr int CV = NOUT / 32;  // cols per thread (4 or 2)
    __shared__ float xs[BM][KC + 1];
    __shared__ __align__(16) float ws[KC][NOUT];

    const int tid = threadIdx.x;
    const int tx = tid & 31;
    const int ty = tid >> 5;
    const int row0 = blockIdx.x * BM;

    float acc[8][CV];
#pragma unroll
    for (int i = 0; i < 8; i++)
#pragma unroll
        for (int j = 0; j < CV; j++) acc[i][j] = 0.f;

    for (int kc = 0; kc < K / KC; kc++) {
#pragma unroll
        for (int i = 0; i < (BM * KC) / 256; i++) {
            int idx = tid + i * 256;
            int r = idx >> 5, c = idx & 31;
            int gr = row0 + r;
            xs[r][c] = (gr < NN) ? X[gr * K + kc * KC + c] : 0.f;
        }
#pragma unroll
        for (int i = 0; i < (KC * NOUT) / 256; i++) {
            int idx = tid + i * 256;
            int r = idx / NOUT, c = idx % NOUT;
            ws[r][c] = W[(kc * KC + r) * NOUT + c];
        }
        __syncthreads();
#pragma unroll
        for (int k = 0; k < KC; k++) {
            float b[CV];
            if constexpr (CV == 4) {
                float4 bv = reinterpret_cast<const float4*>(&ws[k][0])[tx];
                b[0] = bv.x; b[1] = bv.y; b[2] = bv.z; b[3] = bv.w;
            } else {
                float2 bv = reinterpret_cast<const float2*>(&ws[k][0])[tx];
                b[0] = bv.x; b[1] = bv.y;
            }
#pragma unroll
            for (int i = 0; i < 8; i++) {
                float a = xs[ty * 8 + i][k];
#pragma unroll
                for (int j = 0; j < CV; j++) acc[i][j] += a * b[j];
            }
        }
        __syncthreads();
    }

    float as_[CV], ad_[CV];
#pragma unroll
    for (int j = 0; j < CV; j++) {
        as_[j] = ASRC[tx * CV + j];
        ad_[j] = ADST[tx * CV + j];
    }

#pragma unroll
    for (int i = 0; i < 8; i++) {
        int row = row0 + ty * 8 + i;
        float ps = 0.f, pd = 0.f;
#pragma unroll
        for (int j = 0; j < CV; j++) {
            ps += acc[i][j] * as_[j];
            pd += acc[i][j] * ad_[j];
        }
#pragma unroll
        for (int off = 4; off >= 1; off >>= 1) {
            ps += __shfl_xor_sync(0xffffffffu, ps, off);
            pd += __shfl_xor_sync(0xffffffffu, pd, off);
        }
        if (row < NN) {
            if constexpr (CV == 4) {
                float4 o = make_float4(acc[i][0], acc[i][1], acc[i][2], acc[i][3]);
                *reinterpret_cast<float4*>(&Y[row * NOUT + tx * 4]) = o;
            } else {
                float2 o = make_float2(acc[i][0], acc[i][1]);
                *reinterpret_cast<float2*>(&Y[row * NOUT + tx * 2]) = o;
            }
            if ((tx & 7) == 0) {
                asrc[row * 4 + (tx >> 3)] = ps;
                adst[row * 4 + (tx >> 3)] = pd;
            }
        }
    }
}

// ---------- layer-1 gather aggregation: warp/node, fused norm+bias+ELU ------
__global__ void gather1_kernel(const float* __restrict__ h, const float* __restrict__ asrc,
                               const float* __restrict__ adst,
                               const int* __restrict__ rowptr, const int* __restrict__ esrc,
                               const float* __restrict__ b1, float* __restrict__ out) {
    int node = (blockIdx.x * blockDim.x + threadIdx.x) >> 5;
    if (node >= NN) return;
    int lane = threadIdx.x & 31, head = lane >> 3;
    int rs = rowptr[node], re = rowptr[node + 1];
    float ad = adst[node * 4 + head];

    float4 acc = make_float4(0.f, 0.f, 0.f, 0.f);
    float den = 0.f;
    int e = rs;
    while (e + 2 <= re) {
        int s0 = esrc[e], s1 = esrc[e + 1];
        float a0 = asrc[s0 * 4 + head];
        float a1 = asrc[s1 * 4 + head];
        float4 h0 = *reinterpret_cast<const float4*>(h + (size_t)s0 * 128 + lane * 4);
        float4 h1 = *reinterpret_cast<const float4*>(h + (size_t)s1 * 128 + lane * 4);
        float w0 = expf(lrelu(a0 + ad));
        float w1 = expf(lrelu(a1 + ad));
        acc.x += w0 * h0.x + w1 * h1.x;
        acc.y += w0 * h0.y + w1 * h1.y;
        acc.z += w0 * h0.z + w1 * h1.z;
        acc.w += w0 * h0.w + w1 * h1.w;
        den += w0 + w1;
        e += 2;
    }
    if (e < re) {
        int s0 = esrc[e];
        float w0 = expf(lrelu(asrc[s0 * 4 + head] + ad));
        float4 h0 = *reinterpret_cast<const float4*>(h + (size_t)s0 * 128 + lane * 4);
        acc.x += w0 * h0.x; acc.y += w0 * h0.y;
        acc.z += w0 * h0.z; acc.w += w0 * h0.w;
        den += w0;
    }
    float inv = 1.f / (den + 1e-16f);
    float4 b = reinterpret_cast<const float4*>(b1)[lane];
    float4 o;
    o.x = acc.x * inv + b.x; o.y = acc.y * inv + b.y;
    o.z = acc.z * inv + b.z; o.w = acc.w * inv + b.w;
    o.x = o.x > 0.f ? o.x : expm1f(o.x);
    o.y = o.y > 0.f ? o.y : expm1f(o.y);
    o.z = o.z > 0.f ? o.z : expm1f(o.z);
    o.w = o.w > 0.f ? o.w : expm1f(o.w);
    reinterpret_cast<float4*>(out + (size_t)node * 128)[lane] = o;
}

// ---- layer-2 gather aggregation: warp/node, fused norm+bias+log_softmax ----
__global__ void gather2_kernel(const float* __restrict__ h, const float* __restrict__ asrc,
                               const float* __restrict__ adst,
                               const int* __restrict__ rowptr, const int* __restrict__ esrc,
                               const float* __restrict__ b2, float* __restrict__ out) {
    int node = (blockIdx.x * blockDim.x + threadIdx.x) >> 5;
    if (node >= NN) return;
    int lane = threadIdx.x & 31, head = lane >> 3;  // 16 feats/head, 2 feats/lane
    int rs = rowptr[node], re = rowptr[node + 1];
    float ad = adst[node * 4 + head];

    float2 acc = make_float2(0.f, 0.f);
    float den = 0.f;
    int e = rs;
    while (e + 2 <= re) {
        int s0 = esrc[e], s1 = esrc[e + 1];
        float a0 = asrc[s0 * 4 + head];
        float a1 = asrc[s1 * 4 + head];
        float2 h0 = *reinterpret_cast<const float2*>(h + (size_t)s0 * 64 + lane * 2);
        float2 h1 = *reinterpret_cast<const float2*>(h + (size_t)s1 * 64 + lane * 2);
        float w0 = expf(lrelu(a0 + ad));
        float w1 = expf(lrelu(a1 + ad));
        acc.x += w0 * h0.x + w1 * h1.x;
        acc.y += w0 * h0.y + w1 * h1.y;
        den += w0 + w1;
        e += 2;
    }
    if (e < re) {
        int s0 = esrc[e];
        float w0 = expf(lrelu(asrc[s0 * 4 + head] + ad));
        float2 h0 = *reinterpret_cast<const float2*>(h + (size_t)s0 * 64 + lane * 2);
        acc.x += w0 * h0.x; acc.y += w0 * h0.y;
        den += w0;
    }
    float inv = 1.f / (den + 1e-16f);
    float2 b = reinterpret_cast<const float2*>(b2)[lane];
    float2 v;
    v.x = acc.x * inv + b.x;
    v.y = acc.y * inv + b.y;

    // log_softmax over the 64 classes held by this warp
    float mx = fmaxf(v.x, v.y);
#pragma unroll
    for (int off = 16; off >= 1; off >>= 1)
        mx = fmaxf(mx, __shfl_xor_sync(0xffffffffu, mx, off));
    float sm = expf(v.x - mx) + expf(v.y - mx);
#pragma unroll
    for (int off = 16; off >= 1; off >>= 1)
        sm += __shfl_xor_sync(0xffffffffu, sm, off);
    float ls = logf(sm);
    float2 o = make_float2(v.x - mx - ls, v.y - mx - ls);
    *reinterpret_cast<float2*>(out + (size_t)node * 64 + lane * 2) = o;
}

// ------------------------- launch --------------------------------------------
extern "C" void kernel_launch(void* const* d_in, const int* in_sizes, int n_in,
                              void* d_out, int out_size) {
    const float* x        = (const float*)d_in[0];
    const int*   ei       = (const int*)d_in[1];
    const float* W1       = (const float*)d_in[2];
    const float* att_src1 = (const float*)d_in[3];
    const float* att_dst1 = (const float*)d_in[4];
    const float* b1       = (const float*)d_in[5];
    const float* W2       = (const float*)d_in[6];
    const float* att_src2 = (const float*)d_in[7];
    const float* att_dst2 = (const float*)d_in[8];
    const float* b2       = (const float*)d_in[9];
    float* out = (float*)d_out;

    float *h1, *agg1, *h2, *asrc1, *adst1, *asrc2, *adst2;
    int *deg, *wptr, *rowptr, *esrc;
    cudaGetSymbolAddress((void**)&h1, g_h1);
    cudaGetSymbolAddress((void**)&agg1, g_agg1);
    cudaGetSymbolAddress((void**)&h2, g_h2);
    cudaGetSymbolAddress((void**)&asrc1, g_asrc1);
    cudaGetSymbolAddress((void**)&adst1, g_adst1);
    cudaGetSymbolAddress((void**)&asrc2, g_asrc2);
    cudaGetSymbolAddress((void**)&adst2, g_adst2);
    cudaGetSymbolAddress((void**)&deg, g_deg);
    cudaGetSymbolAddress((void**)&wptr, g_wptr);
    cudaGetSymbolAddress((void**)&rowptr, g_rowptr);
    cudaGetSymbolAddress((void**)&esrc, g_esrc);

    const int TB = 256;
    const int gemm_blocks = (NN + 63) / 64;
    const int node_warp_blocks = (NN * 32 + TB - 1) / TB;

    // ---- CSR build (dst-sorted; shared by both layers) ----
    init_deg_kernel<<<(NN + TB - 1) / TB, TB>>>(deg);
    hist_kernel<<<(EIN + TB - 1) / TB, TB>>>(ei, deg);
    scan_kernel<<<1, 1024>>>(deg, rowptr, wptr);
    scatter_kernel<<<(ETOT + TB - 1) / TB, TB>>>(ei, wptr, esrc);

    // ---- layer 1 ----
    gemm_kernel<128><<<gemm_blocks, TB>>>(x, W1, att_src1, att_dst1, h1, asrc1, adst1);
    gather1_kernel<<<node_warp_blocks, TB>>>(h1, asrc1, adst1, rowptr, esrc, b1, agg1);

    // ---- layer 2 ----
    gemm_kernel<64><<<gemm_blocks, TB>>>(agg1, W2, att_src2, att_dst2, h2, asrc2, adst2);
    gather2_kernel<<<node_warp_blocks, TB>>>(h2, asrc2, adst2, rowptr, esrc, b2, out);
}

// round 6
// speedup vs baseline: 2.1425x; 1.0718x over previous
#include <cuda_runtime.h>
#include <math.h>
#include <stdint.h>

#define NN 100000
#define EIN 1600000
#define ETOT (EIN + NN)

// ------------------------- scratch (static device globals) -------------------
__device__ float g_h1[NN * 128];    // layer1 linear out  [N,4,32]
__device__ float g_agg1[NN * 128];  // layer1 GAT out (normalized, biased, ELU)
__device__ float g_h2[NN * 64];     // layer2 linear out  [N,4,16]
__device__ float g_asrc1[NN * 4], g_adst1[NN * 4];
__device__ float g_asrc2[NN * 4], g_adst2[NN * 4];
__device__ int   g_deg[NN + 1];
__device__ int   g_wptr[NN + 1];
__device__ int   g_rowptr[NN + 1];
__device__ int   g_esrc[ETOT];
__device__ float g_w1f[128 * 128];  // W1 in B-fragment order
__device__ float g_w2f[128 * 64];   // W2 in B-fragment order

// ------------------------- helpers -------------------------------------------
__device__ __forceinline__ float lrelu(float x) { return x > 0.f ? x : 0.2f * x; }

__device__ __forceinline__ uint32_t f2tf32(float x) {
    uint32_t r;
    asm("cvt.rna.tf32.f32 %0, %1;" : "=r"(r) : "f"(x));
    return r;
}

__device__ __forceinline__ void mma_tf32(float c[4], uint32_t a0, uint32_t a1,
                                         uint32_t a2, uint32_t a3,
                                         uint32_t b0, uint32_t b1) {
    asm volatile(
        "mma.sync.aligned.m16n8k8.row.col.f32.tf32.tf32.f32 "
        "{%0,%1,%2,%3}, {%4,%5,%6,%7}, {%8,%9}, {%0,%1,%2,%3};"
        : "+f"(c[0]), "+f"(c[1]), "+f"(c[2]), "+f"(c[3])
        : "r"(a0), "r"(a1), "r"(a2), "r"(a3), "r"(b0), "r"(b1));
}

// ------------------------- CSR build -----------------------------------------
__global__ void init_deg_kernel(int* __restrict__ deg) {
    int i = blockIdx.x * blockDim.x + threadIdx.x;
    if (i < NN) deg[i] = 1;  // self loop
}

__global__ void hist_kernel(const int* __restrict__ ei, int* __restrict__ deg) {
    int e = blockIdx.x * blockDim.x + threadIdx.x;
    if (e < EIN) atomicAdd(&deg[ei[EIN + e]], 1);
}

__global__ void scan_kernel(const int* __restrict__ deg, int* __restrict__ rowptr,
                            int* __restrict__ wptr) {
    __shared__ int psum[1024];
    const int t = threadIdx.x;
    const int CH = (NN + 1023) / 1024;
    const int base = t * CH;
    int sum = 0;
    for (int i = 0; i < CH; i++) {
        int idx = base + i;
        if (idx < NN) sum += deg[idx];
    }
    psum[t] = sum;
    __syncthreads();
    for (int off = 1; off < 1024; off <<= 1) {
        int v = (t >= off) ? psum[t - off] : 0;
        __syncthreads();
        psum[t] += v;
        __syncthreads();
    }
    int running = psum[t] - sum;
    for (int i = 0; i < CH; i++) {
        int idx = base + i;
        if (idx < NN) {
            int dv = deg[idx];
            rowptr[idx] = running;
            wptr[idx] = running;
            running += dv;
        }
    }
    if (t == 0) rowptr[NN] = ETOT;
}

__global__ void scatter_kernel(const int* __restrict__ ei, int* __restrict__ wptr,
                               int* __restrict__ esrc) {
    int e = blockIdx.x * blockDim.x + threadIdx.x;
    if (e >= ETOT) return;
    int s, d;
    if (e < EIN) { s = ei[e]; d = ei[EIN + e]; } else { s = d = e - EIN; }
    int pos = atomicAdd(&wptr[d], 1);
    esrc[pos] = s;
}

// --------------- W reorder into mma B-fragment order -------------------------
// Wf[((kk*NT + nt)*32 + lane)*2 + {0,1}]:
//   b0 = W[kk*8 + lane%4][nt*8 + lane/4], b1 = W[kk*8 + lane%4 + 4][nt*8 + lane/4]
__global__ void reorderW_kernel(const float* __restrict__ W, float* __restrict__ Wf,
                                int NOUT) {
    int NT = NOUT / 8;
    int i = blockIdx.x * blockDim.x + threadIdx.x;
    if (i >= 16 * NT * 32) return;
    int lane = i & 31;
    int nt = (i >> 5) % NT;
    int kk = (i >> 5) / NT;
    int krow = kk * 8 + (lane & 3);
    int ncol = nt * 8 + (lane >> 2);
    Wf[i * 2 + 0] = __uint_as_float(f2tf32(W[krow * NOUT + ncol]));
    Wf[i * 2 + 1] = __uint_as_float(f2tf32(W[(krow + 4) * NOUT + ncol]));
}

// --------- tf32 tensor-core GEMM + fused attention-coefficient epilogue ------
// Y[N, NOUT] = X[N,128] @ W[128,NOUT]; 128 rows/block, 8 warps, warp = 16 rows.
template <int NOUT>
__global__ void gemm_tc_kernel(const float* __restrict__ X, const float* __restrict__ Wf,
                               const float* __restrict__ ASRC, const float* __restrict__ ADST,
                               float* __restrict__ Y,
                               float* __restrict__ asrc, float* __restrict__ adst) {
    constexpr int NT = NOUT / 8;    // n-tiles of 8
    constexpr int NTH = NT / 4;     // n-tiles per head
    extern __shared__ float smem[];
    float* xs = smem;               // 128*128 floats, A-fragment order
    float* wf = smem + 128 * 128;   // 128*NOUT floats, B-fragment order

    const int tid = threadIdx.x;
    const int w = tid >> 5;
    const int lane = tid & 31;
    const int row0b = blockIdx.x * 128;

    // stage W fragments (linear, coalesced)
#pragma unroll 4
    for (int i = tid; i < NOUT * 128 / 4; i += 256)
        reinterpret_cast<float4*>(wf)[i] = reinterpret_cast<const float4*>(Wf)[i];

    // stage X into A-fragment order (+ tf32 rounding)
#pragma unroll
    for (int it = 0; it < 16; it++) {
        int idx = tid + it * 256;   // over 128 rows x 32 float4
        int rl = idx >> 5;
        int j = idx & 31;
        int gr = row0b + rl;
        float4 v = (gr < NN) ? reinterpret_cast<const float4*>(X + (size_t)gr * 128)[j]
                             : make_float4(0.f, 0.f, 0.f, 0.f);
        int ww = rl >> 4, r = rl & 15;
        int kk = j >> 1;
        int reg = ((j & 1) << 1) | (r >> 3);
        float* base = xs + (((ww * 16 + kk) * 32 + ((r & 7) << 2)) << 2) + reg;
        base[0]  = __uint_as_float(f2tf32(v.x));
        base[4]  = __uint_as_float(f2tf32(v.y));
        base[8]  = __uint_as_float(f2tf32(v.z));
        base[12] = __uint_as_float(f2tf32(v.w));
    }
    __syncthreads();

    float acc[NT][4];
#pragma unroll
    for (int nt = 0; nt < NT; nt++)
#pragma unroll
        for (int j = 0; j < 4; j++) acc[nt][j] = 0.f;

#pragma unroll
    for (int kk = 0; kk < 16; kk++) {
        float4 af = reinterpret_cast<const float4*>(xs)[(w * 16 + kk) * 32 + lane];
        uint32_t a0 = __float_as_uint(af.x), a1 = __float_as_uint(af.y);
        uint32_t a2 = __float_as_uint(af.z), a3 = __float_as_uint(af.w);
        const float2* bb = reinterpret_cast<const float2*>(wf) + (kk * NT) * 32 + lane;
#pragma unroll
        for (int nt = 0; nt < NT; nt++) {
            float2 bf = bb[nt * 32];
            mma_tf32(acc[nt], a0, a1, a2, a3,
                     __float_as_uint(bf.x), __float_as_uint(bf.y));
        }
    }

    // epilogue: Y rows + per-head attention dots
    int r0 = row0b + w * 16 + (lane >> 2);
    int r1 = r0 + 8;
    float ps0[4] = {0, 0, 0, 0}, pd0[4] = {0, 0, 0, 0};
    float ps1[4] = {0, 0, 0, 0}, pd1[4] = {0, 0, 0, 0};
#pragma unroll
    for (int nt = 0; nt < NT; nt++) {
        int col = nt * 8 + (lane & 3) * 2;
        float s0 = __ldg(ASRC + col), s1 = __ldg(ASRC + col + 1);
        float d0 = __ldg(ADST + col), d1 = __ldg(ADST + col + 1);
        int h = nt / NTH;
        ps0[h] += acc[nt][0] * s0 + acc[nt][1] * s1;
        pd0[h] += acc[nt][0] * d0 + acc[nt][1] * d1;
        ps1[h] += acc[nt][2] * s0 + acc[nt][3] * s1;
        pd1[h] += acc[nt][2] * d0 + acc[nt][3] * d1;
        if (r0 < NN)
            *reinterpret_cast<float2*>(&Y[(size_t)r0 * NOUT + col]) =
                make_float2(acc[nt][0], acc[nt][1]);
        if (r1 < NN)
            *reinterpret_cast<float2*>(&Y[(size_t)r1 * NOUT + col]) =
                make_float2(acc[nt][2], acc[nt][3]);
    }
#pragma unroll
    for (int off = 1; off <= 2; off <<= 1) {
#pragma unroll
        for (int h = 0; h < 4; h++) {
            ps0[h] += __shfl_xor_sync(0xffffffffu, ps0[h], off);
            pd0[h] += __shfl_xor_sync(0xffffffffu, pd0[h], off);
            ps1[h] += __shfl_xor_sync(0xffffffffu, ps1[h], off);
            pd1[h] += __shfl_xor_sync(0xffffffffu, pd1[h], off);
        }
    }
    if ((lane & 3) == 0) {
        if (r0 < NN)
#pragma unroll
            for (int h = 0; h < 4; h++) {
                asrc[r0 * 4 + h] = ps0[h];
                adst[r0 * 4 + h] = pd0[h];
            }
        if (r1 < NN)
#pragma unroll
            for (int h = 0; h < 4; h++) {
                asrc[r1 * 4 + h] = ps1[h];
                adst[r1 * 4 + h] = pd1[h];
            }
    }
}

// ---------- layer-1 gather aggregation: warp/node, fused norm+bias+ELU ------
__global__ void gather1_kernel(const float* __restrict__ h, const float* __restrict__ asrc,
                               const float* __restrict__ adst,
                               const int* __restrict__ rowptr, const int* __restrict__ esrc,
                               const float* __restrict__ b1, float* __restrict__ out) {
    int node = (blockIdx.x * blockDim.x + threadIdx.x) >> 5;
    if (node >= NN) return;
    int lane = threadIdx.x & 31, head = lane >> 3;
    int rs = rowptr[node], re = rowptr[node + 1];
    float ad = adst[node * 4 + head];

    float4 acc = make_float4(0.f, 0.f, 0.f, 0.f);
    float den = 0.f;
    int e = rs;
    while (e + 2 <= re) {
        int s0 = esrc[e], s1 = esrc[e + 1];
        float a0 = asrc[s0 * 4 + head];
        float a1 = asrc[s1 * 4 + head];
        float4 h0 = *reinterpret_cast<const float4*>(h + (size_t)s0 * 128 + lane * 4);
        float4 h1 = *reinterpret_cast<const float4*>(h + (size_t)s1 * 128 + lane * 4);
        float w0 = expf(lrelu(a0 + ad));
        float w1 = expf(lrelu(a1 + ad));
        acc.x += w0 * h0.x + w1 * h1.x;
        acc.y += w0 * h0.y + w1 * h1.y;
        acc.z += w0 * h0.z + w1 * h1.z;
        acc.w += w0 * h0.w + w1 * h1.w;
        den += w0 + w1;
        e += 2;
    }
    if (e < re) {
        int s0 = esrc[e];
        float w0 = expf(lrelu(asrc[s0 * 4 + head] + ad));
        float4 h0 = *reinterpret_cast<const float4*>(h + (size_t)s0 * 128 + lane * 4);
        acc.x += w0 * h0.x; acc.y += w0 * h0.y;
        acc.z += w0 * h0.z; acc.w += w0 * h0.w;
        den += w0;
    }
    float inv = 1.f / (den + 1e-16f);
    float4 b = reinterpret_cast<const float4*>(b1)[lane];
    float4 o;
    o.x = acc.x * inv + b.x; o.y = acc.y * inv + b.y;
    o.z = acc.z * inv + b.z; o.w = acc.w * inv + b.w;
    o.x = o.x > 0.f ? o.x : expm1f(o.x);
    o.y = o.y > 0.f ? o.y : expm1f(o.y);
    o.z = o.z > 0.f ? o.z : expm1f(o.z);
    o.w = o.w > 0.f ? o.w : expm1f(o.w);
    reinterpret_cast<float4*>(out + (size_t)node * 128)[lane] = o;
}

// ---- layer-2 gather aggregation: warp/node, fused norm+bias+log_softmax ----
__global__ void gather2_kernel(const float* __restrict__ h, const float* __restrict__ asrc,
                               const float* __restrict__ adst,
                               const int* __restrict__ rowptr, const int* __restrict__ esrc,
                               const float* __restrict__ b2, float* __restrict__ out) {
    int node = (blockIdx.x * blockDim.x + threadIdx.x) >> 5;
    if (node >= NN) return;
    int lane = threadIdx.x & 31, head = lane >> 3;
    int rs = rowptr[node], re = rowptr[node + 1];
    float ad = adst[node * 4 + head];

    float2 acc = make_float2(0.f, 0.f);
    float den = 0.f;
    int e = rs;
    while (e + 2 <= re) {
        int s0 = esrc[e], s1 = esrc[e + 1];
        float a0 = asrc[s0 * 4 + head];
        float a1 = asrc[s1 * 4 + head];
        float2 h0 = *reinterpret_cast<const float2*>(h + (size_t)s0 * 64 + lane * 2);
        float2 h1 = *reinterpret_cast<const float2*>(h + (size_t)s1 * 64 + lane * 2);
        float w0 = expf(lrelu(a0 + ad));
        float w1 = expf(lrelu(a1 + ad));
        acc.x += w0 * h0.x + w1 * h1.x;
        acc.y += w0 * h0.y + w1 * h1.y;
        den += w0 + w1;
        e += 2;
    }
    if (e < re) {
        int s0 = esrc[e];
        float w0 = expf(lrelu(asrc[s0 * 4 + head] + ad));
        float2 h0 = *reinterpret_cast<const float2*>(h + (size_t)s0 * 64 + lane * 2);
        acc.x += w0 * h0.x; acc.y += w0 * h0.y;
        den += w0;
    }
    float inv = 1.f / (den + 1e-16f);
    float2 b = reinterpret_cast<const float2*>(b2)[lane];
    float2 v;
    v.x = acc.x * inv + b.x;
    v.y = acc.y * inv + b.y;

    float mx = fmaxf(v.x, v.y);
#pragma unroll
    for (int off = 16; off >= 1; off >>= 1)
        mx = fmaxf(mx, __shfl_xor_sync(0xffffffffu, mx, off));
    float sm = expf(v.x - mx) + expf(v.y - mx);
#pragma unroll
    for (int off = 16; off >= 1; off >>= 1)
        sm += __shfl_xor_sync(0xffffffffu, sm, off);
    float ls = logf(sm);
    float2 o = make_float2(v.x - mx - ls, v.y - mx - ls);
    *reinterpret_cast<float2*>(out + (size_t)node * 64 + lane * 2) = o;
}

// ------------------------- launch --------------------------------------------
extern "C" void kernel_launch(void* const* d_in, const int* in_sizes, int n_in,
                              void* d_out, int out_size) {
    const float* x        = (const float*)d_in[0];
    const int*   ei       = (const int*)d_in[1];
    const float* W1       = (const float*)d_in[2];
    const float* att_src1 = (const float*)d_in[3];
    const float* att_dst1 = (const float*)d_in[4];
    const float* b1       = (const float*)d_in[5];
    const float* W2       = (const float*)d_in[6];
    const float* att_src2 = (const float*)d_in[7];
    const float* att_dst2 = (const float*)d_in[8];
    const float* b2       = (const float*)d_in[9];
    float* out = (float*)d_out;

    float *h1, *agg1, *h2, *asrc1, *adst1, *asrc2, *adst2, *w1f, *w2f;
    int *deg, *wptr, *rowptr, *esrc;
    cudaGetSymbolAddress((void**)&h1, g_h1);
    cudaGetSymbolAddress((void**)&agg1, g_agg1);
    cudaGetSymbolAddress((void**)&h2, g_h2);
    cudaGetSymbolAddress((void**)&asrc1, g_asrc1);
    cudaGetSymbolAddress((void**)&adst1, g_adst1);
    cudaGetSymbolAddress((void**)&asrc2, g_asrc2);
    cudaGetSymbolAddress((void**)&adst2, g_adst2);
    cudaGetSymbolAddress((void**)&deg, g_deg);
    cudaGetSymbolAddress((void**)&wptr, g_wptr);
    cudaGetSymbolAddress((void**)&rowptr, g_rowptr);
    cudaGetSymbolAddress((void**)&esrc, g_esrc);
    cudaGetSymbolAddress((void**)&w1f, g_w1f);
    cudaGetSymbolAddress((void**)&w2f, g_w2f);

    const int TB = 256;
    const int gemm_blocks = (NN + 127) / 128;
    const int node_warp_blocks = (NN * 32 + TB - 1) / TB;
    const int smem1 = (128 * 128 + 128 * 128) * 4;
    const int smem2 = (128 * 128 + 128 * 64) * 4;

    cudaFuncSetAttribute(gemm_tc_kernel<128>,
                         cudaFuncAttributeMaxDynamicSharedMemorySize, smem1);
    cudaFuncSetAttribute(gemm_tc_kernel<64>,
                         cudaFuncAttributeMaxDynamicSharedMemorySize, smem2);

    // ---- weight reorders + CSR build (graph shared by both layers) ----
    reorderW_kernel<<<(16 * 16 * 32 + TB - 1) / TB, TB>>>(W1, w1f, 128);
    reorderW_kernel<<<(16 * 8 * 32 + TB - 1) / TB, TB>>>(W2, w2f, 64);
    init_deg_kernel<<<(NN + TB - 1) / TB, TB>>>(deg);
    hist_kernel<<<(EIN + TB - 1) / TB, TB>>>(ei, deg);
    scan_kernel<<<1, 1024>>>(deg, rowptr, wptr);
    scatter_kernel<<<(ETOT + TB - 1) / TB, TB>>>(ei, wptr, esrc);

    // ---- layer 1 ----
    gemm_tc_kernel<128><<<gemm_blocks, TB, smem1>>>(x, w1f, att_src1, att_dst1,
                                                    h1, asrc1, adst1);
    gather1_kernel<<<node_warp_blocks, TB>>>(h1, asrc1, adst1, rowptr, esrc, b1, agg1);

    // ---- layer 2 ----
    gemm_tc_kernel<64><<<gemm_blocks, TB, smem2>>>(agg1, w2f, att_src2, att_dst2,
                                                   h2, asrc2, adst2);
    gather2_kernel<<<node_warp_blocks, TB>>>(h2, asrc2, adst2, rowptr, esrc, b2, out);
}

// round 7
// speedup vs baseline: 2.4881x; 1.1613x over previous
#include <cuda_runtime.h>
#include <math.h>
#include <stdint.h>

#define NN 100000
#define EIN 1600000
#define ETOT (EIN + NN)

// ------------------------- scratch (static device globals) -------------------
__device__ float g_h1[NN * 128];
__device__ float g_agg1[NN * 128];
__device__ float g_h2[NN * 64];
__device__ float g_asrc1[NN * 4], g_adst1[NN * 4];
__device__ float g_asrc2[NN * 4], g_adst2[NN * 4];
__device__ int   g_deg[NN + 1];
__device__ int   g_wptr[NN + 1];
__device__ int   g_rowptr[NN + 1];
__device__ int   g_esrc[ETOT];
__device__ float g_w1f[128 * 128];
__device__ float g_w2f[128 * 64];

// ------------------------- helpers -------------------------------------------
__device__ __forceinline__ float lrelu(float x) { return x > 0.f ? x : 0.2f * x; }

__device__ __forceinline__ uint32_t f2tf32(float x) {
    uint32_t r;
    asm("cvt.rna.tf32.f32 %0, %1;" : "=r"(r) : "f"(x));
    return r;
}

__device__ __forceinline__ void mma_tf32(float c[4], uint32_t a0, uint32_t a1,
                                         uint32_t a2, uint32_t a3,
                                         uint32_t b0, uint32_t b1) {
    asm volatile(
        "mma.sync.aligned.m16n8k8.row.col.f32.tf32.tf32.f32 "
        "{%0,%1,%2,%3}, {%4,%5,%6,%7}, {%8,%9}, {%0,%1,%2,%3};"
        : "+f"(c[0]), "+f"(c[1]), "+f"(c[2]), "+f"(c[3])
        : "r"(a0), "r"(a1), "r"(a2), "r"(a3), "r"(b0), "r"(b1));
}

// ------------------------- CSR build -----------------------------------------
__global__ void hist_kernel(const int* __restrict__ ei, int* __restrict__ deg) {
    int e2 = blockIdx.x * blockDim.x + threadIdx.x;
    if (e2 * 2 >= EIN) return;
    int2 d = *reinterpret_cast<const int2*>(ei + EIN + e2 * 2);
    atomicAdd(&deg[d.x], 1);
    atomicAdd(&deg[d.y], 1);
}

// deg holds edge-only in-degree; scan adds +1 per node for the self loop
__global__ void scan_kernel(const int* __restrict__ deg, int* __restrict__ rowptr,
                            int* __restrict__ wptr) {
    __shared__ int psum[1024];
    const int t = threadIdx.x;
    const int CH = (NN + 1023) / 1024;
    const int base = t * CH;
    int sum = 0;
    for (int i = 0; i < CH; i++) {
        int idx = base + i;
        if (idx < NN) sum += deg[idx] + 1;
    }
    psum[t] = sum;
    __syncthreads();
    for (int off = 1; off < 1024; off <<= 1) {
        int v = (t >= off) ? psum[t - off] : 0;
        __syncthreads();
        psum[t] += v;
        __syncthreads();
    }
    int running = psum[t] - sum;
    for (int i = 0; i < CH; i++) {
        int idx = base + i;
        if (idx < NN) {
            int dv = deg[idx] + 1;
            rowptr[idx] = running;
            wptr[idx] = running;
            running += dv;
        }
    }
    if (t == 0) rowptr[NN] = ETOT;
}

__global__ void scatter_kernel(const int* __restrict__ ei, int* __restrict__ wptr,
                               int* __restrict__ esrc) {
    int e = blockIdx.x * blockDim.x + threadIdx.x;
    if (e >= ETOT) return;
    int s, d;
    if (e < EIN) { s = ei[e]; d = ei[EIN + e]; } else { s = d = e - EIN; }
    int pos = atomicAdd(&wptr[d], 1);
    esrc[pos] = s;
}

// --------------- W reorder into mma B-fragment order -------------------------
__global__ void reorderW_kernel(const float* __restrict__ W, float* __restrict__ Wf,
                                int NOUT) {
    int NT = NOUT / 8;
    int i = blockIdx.x * blockDim.x + threadIdx.x;
    if (i >= 16 * NT * 32) return;
    int lane = i & 31;
    int nt = (i >> 5) % NT;
    int kk = (i >> 5) / NT;
    int krow = kk * 8 + (lane & 3);
    int ncol = nt * 8 + (lane >> 2);
    Wf[i * 2 + 0] = __uint_as_float(f2tf32(W[krow * NOUT + ncol]));
    Wf[i * 2 + 1] = __uint_as_float(f2tf32(W[(krow + 4) * NOUT + ncol]));
}

// --------- tf32 tensor-core GEMM + fused attention-coefficient epilogue ------
template <int NOUT>
__global__ void gemm_tc_kernel(const float* __restrict__ X, const float* __restrict__ Wf,
                               const float* __restrict__ ASRC, const float* __restrict__ ADST,
                               float* __restrict__ Y,
                               float* __restrict__ asrc, float* __restrict__ adst) {
    constexpr int NT = NOUT / 8;
    constexpr int NTH = NT / 4;
    extern __shared__ float smem[];
    float* xs = smem;
    float* wf = smem + 128 * 128;

    const int tid = threadIdx.x;
    const int w = tid >> 5;
    const int lane = tid & 31;
    const int row0b = blockIdx.x * 128;

#pragma unroll 4
    for (int i = tid; i < NOUT * 128 / 4; i += 256)
        reinterpret_cast<float4*>(wf)[i] = reinterpret_cast<const float4*>(Wf)[i];

#pragma unroll
    for (int it = 0; it < 16; it++) {
        int idx = tid + it * 256;
        int rl = idx >> 5;
        int j = idx & 31;
        int gr = row0b + rl;
        float4 v = (gr < NN) ? reinterpret_cast<const float4*>(X + (size_t)gr * 128)[j]
                             : make_float4(0.f, 0.f, 0.f, 0.f);
        int ww = rl >> 4, r = rl & 15;
        int kk = j >> 1;
        int reg = ((j & 1) << 1) | (r >> 3);
        float* base = xs + (((ww * 16 + kk) * 32 + ((r & 7) << 2)) << 2) + reg;
        base[0]  = __uint_as_float(f2tf32(v.x));
        base[4]  = __uint_as_float(f2tf32(v.y));
        base[8]  = __uint_as_float(f2tf32(v.z));
        base[12] = __uint_as_float(f2tf32(v.w));
    }
    __syncthreads();

    float acc[NT][4];
#pragma unroll
    for (int nt = 0; nt < NT; nt++)
#pragma unroll
        for (int j = 0; j < 4; j++) acc[nt][j] = 0.f;

#pragma unroll
    for (int kk = 0; kk < 16; kk++) {
        float4 af = reinterpret_cast<const float4*>(xs)[(w * 16 + kk) * 32 + lane];
        uint32_t a0 = __float_as_uint(af.x), a1 = __float_as_uint(af.y);
        uint32_t a2 = __float_as_uint(af.z), a3 = __float_as_uint(af.w);
        const float2* bb = reinterpret_cast<const float2*>(wf) + (kk * NT) * 32 + lane;
#pragma unroll
        for (int nt = 0; nt < NT; nt++) {
            float2 bf = bb[nt * 32];
            mma_tf32(acc[nt], a0, a1, a2, a3,
                     __float_as_uint(bf.x), __float_as_uint(bf.y));
        }
    }

    int r0 = row0b + w * 16 + (lane >> 2);
    int r1 = r0 + 8;
    float ps0[4] = {0, 0, 0, 0}, pd0[4] = {0, 0, 0, 0};
    float ps1[4] = {0, 0, 0, 0}, pd1[4] = {0, 0, 0, 0};
#pragma unroll
    for (int nt = 0; nt < NT; nt++) {
        int col = nt * 8 + (lane & 3) * 2;
        float s0 = __ldg(ASRC + col), s1 = __ldg(ASRC + col + 1);
        float d0 = __ldg(ADST + col), d1 = __ldg(ADST + col + 1);
        int h = nt / NTH;
        ps0[h] += acc[nt][0] * s0 + acc[nt][1] * s1;
        pd0[h] += acc[nt][0] * d0 + acc[nt][1] * d1;
        ps1[h] += acc[nt][2] * s0 + acc[nt][3] * s1;
        pd1[h] += acc[nt][2] * d0 + acc[nt][3] * d1;
        if (r0 < NN)
            *reinterpret_cast<float2*>(&Y[(size_t)r0 * NOUT + col]) =
                make_float2(acc[nt][0], acc[nt][1]);
        if (r1 < NN)
            *reinterpret_cast<float2*>(&Y[(size_t)r1 * NOUT + col]) =
                make_float2(acc[nt][2], acc[nt][3]);
    }
#pragma unroll
    for (int off = 1; off <= 2; off <<= 1) {
#pragma unroll
        for (int h = 0; h < 4; h++) {
            ps0[h] += __shfl_xor_sync(0xffffffffu, ps0[h], off);
            pd0[h] += __shfl_xor_sync(0xffffffffu, pd0[h], off);
            ps1[h] += __shfl_xor_sync(0xffffffffu, ps1[h], off);
            pd1[h] += __shfl_xor_sync(0xffffffffu, pd1[h], off);
        }
    }
    if ((lane & 3) == 0) {
        if (r0 < NN)
#pragma unroll
            for (int h = 0; h < 4; h++) {
                asrc[r0 * 4 + h] = ps0[h];
                adst[r0 * 4 + h] = pd0[h];
            }
        if (r1 < NN)
#pragma unroll
            for (int h = 0; h < 4; h++) {
                asrc[r1 * 4 + h] = ps1[h];
                adst[r1 * 4 + h] = pd1[h];
            }
    }
}

// ---------- layer-1 gather aggregation: warp/node, 4x unroll, fused epilogue -
__global__ void gather1_kernel(const float* __restrict__ h, const float* __restrict__ asrc,
                               const float* __restrict__ adst,
                               const int* __restrict__ rowptr, const int* __restrict__ esrc,
                               const float* __restrict__ b1, float* __restrict__ out) {
    int node = (blockIdx.x * blockDim.x + threadIdx.x) >> 5;
    if (node >= NN) return;
    int lane = threadIdx.x & 31, head = lane >> 3;
    int rs = rowptr[node], re = rowptr[node + 1];
    float ad = adst[node * 4 + head];

    float4 acc = make_float4(0.f, 0.f, 0.f, 0.f);
    float den = 0.f;
    int e = rs;
    while (e + 4 <= re) {
        int s0 = esrc[e], s1 = esrc[e + 1], s2 = esrc[e + 2], s3 = esrc[e + 3];
        float4 h0 = *reinterpret_cast<const float4*>(h + (size_t)s0 * 128 + lane * 4);
        float4 h1 = *reinterpret_cast<const float4*>(h + (size_t)s1 * 128 + lane * 4);
        float4 h2 = *reinterpret_cast<const float4*>(h + (size_t)s2 * 128 + lane * 4);
        float4 h3 = *reinterpret_cast<const float4*>(h + (size_t)s3 * 128 + lane * 4);
        float w0 = expf(lrelu(asrc[s0 * 4 + head] + ad));
        float w1 = expf(lrelu(asrc[s1 * 4 + head] + ad));
        float w2 = expf(lrelu(asrc[s2 * 4 + head] + ad));
        float w3 = expf(lrelu(asrc[s3 * 4 + head] + ad));
        acc.x += w0 * h0.x + w1 * h1.x + w2 * h2.x + w3 * h3.x;
        acc.y += w0 * h0.y + w1 * h1.y + w2 * h2.y + w3 * h3.y;
        acc.z += w0 * h0.z + w1 * h1.z + w2 * h2.z + w3 * h3.z;
        acc.w += w0 * h0.w + w1 * h1.w + w2 * h2.w + w3 * h3.w;
        den += w0 + w1 + w2 + w3;
        e += 4;
    }
    while (e < re) {
        int s0 = esrc[e];
        float w0 = expf(lrelu(asrc[s0 * 4 + head] + ad));
        float4 h0 = *reinterpret_cast<const float4*>(h + (size_t)s0 * 128 + lane * 4);
        acc.x += w0 * h0.x; acc.y += w0 * h0.y;
        acc.z += w0 * h0.z; acc.w += w0 * h0.w;
        den += w0;
        e++;
    }
    float inv = 1.f / (den + 1e-16f);
    float4 b = reinterpret_cast<const float4*>(b1)[lane];
    float4 o;
    o.x = acc.x * inv + b.x; o.y = acc.y * inv + b.y;
    o.z = acc.z * inv + b.z; o.w = acc.w * inv + b.w;
    o.x = o.x > 0.f ? o.x : expm1f(o.x);
    o.y = o.y > 0.f ? o.y : expm1f(o.y);
    o.z = o.z > 0.f ? o.z : expm1f(o.z);
    o.w = o.w > 0.f ? o.w : expm1f(o.w);
    reinterpret_cast<float4*>(out + (size_t)node * 128)[lane] = o;
}

// ---- layer-2 gather: warp/node, 4x unroll, fused norm+bias+log_softmax -----
__global__ void gather2_kernel(const float* __restrict__ h, const float* __restrict__ asrc,
                               const float* __restrict__ adst,
                               const int* __restrict__ rowptr, const int* __restrict__ esrc,
                               const float* __restrict__ b2, float* __restrict__ out) {
    int node = (blockIdx.x * blockDim.x + threadIdx.x) >> 5;
    if (node >= NN) return;
    int lane = threadIdx.x & 31, head = lane >> 3;
    int rs = rowptr[node], re = rowptr[node + 1];
    float ad = adst[node * 4 + head];

    float2 acc = make_float2(0.f, 0.f);
    float den = 0.f;
    int e = rs;
    while (e + 4 <= re) {
        int s0 = esrc[e], s1 = esrc[e + 1], s2 = esrc[e + 2], s3 = esrc[e + 3];
        float2 h0 = *reinterpret_cast<const float2*>(h + (size_t)s0 * 64 + lane * 2);
        float2 h1 = *reinterpret_cast<const float2*>(h + (size_t)s1 * 64 + lane * 2);
        float2 h2 = *reinterpret_cast<const float2*>(h + (size_t)s2 * 64 + lane * 2);
        float2 h3 = *reinterpret_cast<const float2*>(h + (size_t)s3 * 64 + lane * 2);
        float w0 = expf(lrelu(asrc[s0 * 4 + head] + ad));
        float w1 = expf(lrelu(asrc[s1 * 4 + head] + ad));
        float w2 = expf(lrelu(asrc[s2 * 4 + head] + ad));
        float w3 = expf(lrelu(asrc[s3 * 4 + head] + ad));
        acc.x += w0 * h0.x + w1 * h1.x + w2 * h2.x + w3 * h3.x;
        acc.y += w0 * h0.y + w1 * h1.y + w2 * h2.y + w3 * h3.y;
        den += w0 + w1 + w2 + w3;
        e += 4;
    }
    while (e < re) {
        int s0 = esrc[e];
        float w0 = expf(lrelu(asrc[s0 * 4 + head] + ad));
        float2 h0 = *reinterpret_cast<const float2*>(h + (size_t)s0 * 64 + lane * 2);
        acc.x += w0 * h0.x; acc.y += w0 * h0.y;
        den += w0;
        e++;
    }
    float inv = 1.f / (den + 1e-16f);
    float2 b = reinterpret_cast<const float2*>(b2)[lane];
    float2 v;
    v.x = acc.x * inv + b.x;
    v.y = acc.y * inv + b.y;

    float mx = fmaxf(v.x, v.y);
#pragma unroll
    for (int off = 16; off >= 1; off >>= 1)
        mx = fmaxf(mx, __shfl_xor_sync(0xffffffffu, mx, off));
    float sm = expf(v.x - mx) + expf(v.y - mx);
#pragma unroll
    for (int off = 16; off >= 1; off >>= 1)
        sm += __shfl_xor_sync(0xffffffffu, sm, off);
    float ls = logf(sm);
    float2 o = make_float2(v.x - mx - ls, v.y - mx - ls);
    *reinterpret_cast<float2*>(out + (size_t)node * 64 + lane * 2) = o;
}

// ------------------------- launch --------------------------------------------
extern "C" void kernel_launch(void* const* d_in, const int* in_sizes, int n_in,
                              void* d_out, int out_size) {
    const float* x        = (const float*)d_in[0];
    const int*   ei       = (const int*)d_in[1];
    const float* W1       = (const float*)d_in[2];
    const float* att_src1 = (const float*)d_in[3];
    const float* att_dst1 = (const float*)d_in[4];
    const float* b1       = (const float*)d_in[5];
    const float* W2       = (const float*)d_in[6];
    const float* att_src2 = (const float*)d_in[7];
    const float* att_dst2 = (const float*)d_in[8];
    const float* b2       = (const float*)d_in[9];
    float* out = (float*)d_out;

    float *h1, *agg1, *h2, *asrc1, *adst1, *asrc2, *adst2, *w1f, *w2f;
    int *deg, *wptr, *rowptr, *esrc;
    cudaGetSymbolAddress((void**)&h1, g_h1);
    cudaGetSymbolAddress((void**)&agg1, g_agg1);
    cudaGetSymbolAddress((void**)&h2, g_h2);
    cudaGetSymbolAddress((void**)&asrc1, g_asrc1);
    cudaGetSymbolAddress((void**)&adst1, g_adst1);
    cudaGetSymbolAddress((void**)&asrc2, g_asrc2);
    cudaGetSymbolAddress((void**)&adst2, g_adst2);
    cudaGetSymbolAddress((void**)&deg, g_deg);
    cudaGetSymbolAddress((void**)&wptr, g_wptr);
    cudaGetSymbolAddress((void**)&rowptr, g_rowptr);
    cudaGetSymbolAddress((void**)&esrc, g_esrc);
    cudaGetSymbolAddress((void**)&w1f, g_w1f);
    cudaGetSymbolAddress((void**)&w2f, g_w2f);

    const int TB = 256;
    const int gemm_blocks = (NN + 127) / 128;
    const int node_warp_blocks = (NN * 32 + TB - 1) / TB;
    const int smem1 = (128 * 128 + 128 * 128) * 4;
    const int smem2 = (128 * 128 + 128 * 64) * 4;

    cudaFuncSetAttribute(gemm_tc_kernel<128>,
                         cudaFuncAttributeMaxDynamicSharedMemorySize, smem1);
    cudaFuncSetAttribute(gemm_tc_kernel<64>,
                         cudaFuncAttributeMaxDynamicSharedMemorySize, smem2);

    // ---- fork a side stream: CSR build runs concurrently with gemm1 --------
    cudaStream_t s2;
    cudaStreamCreateWithFlags(&s2, cudaStreamNonBlocking);
    cudaEvent_t evFork, evJoin;
    cudaEventCreateWithFlags(&evFork, cudaEventDisableTiming);
    cudaEventCreateWithFlags(&evJoin, cudaEventDisableTiming);

    cudaEventRecord(evFork, 0);
    cudaStreamWaitEvent(s2, evFork, 0);

    // side stream: CSR build chain
    cudaMemsetAsync(deg, 0, (NN + 1) * sizeof(int), s2);
    hist_kernel<<<(EIN / 2 + TB - 1) / TB, TB, 0, s2>>>(ei, deg);
    scan_kernel<<<1, 1024, 0, s2>>>(deg, rowptr, wptr);
    scatter_kernel<<<(ETOT + TB - 1) / TB, TB, 0, s2>>>(ei, wptr, esrc);
    cudaEventRecord(evJoin, s2);

    // main stream: weight reorders + layer-1 GEMM (no CSR dependence)
    reorderW_kernel<<<(16 * 16 * 32 + TB - 1) / TB, TB>>>(W1, w1f, 128);
    reorderW_kernel<<<(16 * 8 * 32 + TB - 1) / TB, TB>>>(W2, w2f, 64);
    gemm_tc_kernel<128><<<gemm_blocks, TB, smem1>>>(x, w1f, att_src1, att_dst1,
                                                    h1, asrc1, adst1);

    // join: gather1 needs both gemm1 outputs and the CSR
    cudaStreamWaitEvent(0, evJoin, 0);
    gather1_kernel<<<node_warp_blocks, TB>>>(h1, asrc1, adst1, rowptr, esrc, b1, agg1);

    // ---- layer 2 ----
    gemm_tc_kernel<64><<<gemm_blocks, TB, smem2>>>(agg1, w2f, att_src2, att_dst2,
                                                   h2, asrc2, adst2);
    gather2_kernel<<<node_warp_blocks, TB>>>(h2, asrc2, adst2, rowptr, esrc, b2, out);
}